// round 17
// baseline (speedup 1.0000x reference)
#include <cuda_runtime.h>
#include <cstdint>
#include <math_constants.h>

#define BATCH   16384
#define S       2048
#define G       256
#define NT      256
#define RANKW   1793u
#define RANKL   256u
#define SHW     4.0f
#define SHL    -4.0f
// windows (bins over [-4,4), width 1/32): swv in [0.99,1.31], slv in [-1.31,-0.99]
#define WLO     159
#define WHI     169
#define LLO     86
#define LHI     96
#define WCAP    256
#define FCAP    32

typedef unsigned long long ull;

__device__ __forceinline__ uint32_t f2u(float f) {
    uint32_t b = __float_as_uint(f);
    return b ^ ((b & 0x80000000u) ? 0xFFFFFFFFu : 0x80000000u);
}
__device__ __forceinline__ float u2f(uint32_t u) {
    uint32_t b = (u & 0x80000000u) ? (u ^ 0x80000000u) : ~u;
    return __uint_as_float(b);
}
__device__ __forceinline__ int val2bin(float s) {
    int b = __float2int_rd(fmaf(s, 32.0f, 128.0f));
    return min(max(b, 0), 255);
}

// ---- block exclusive scan (u32), 256 threads (fallback radix) ----
__device__ __forceinline__ uint32_t block_exscan_u32(uint32_t v, uint32_t* st) {
    const uint32_t full = 0xffffffffu;
    int lane = threadIdx.x & 31, w = threadIdx.x >> 5;
    uint32_t inc = v;
#pragma unroll
    for (int o = 1; o < 32; o <<= 1) {
        uint32_t t = __shfl_up_sync(full, inc, o);
        if (lane >= o) inc += t;
    }
    if (lane == 31) st[w] = inc;
    __syncthreads();
    if (threadIdx.x < 32) {
        uint32_t t = (lane < 8) ? st[lane] : 0u;
        uint32_t it = t;
#pragma unroll
        for (int o = 1; o < 8; o <<= 1) {
            uint32_t x = __shfl_up_sync(full, it, o);
            if (lane >= o) it += x;
        }
        if (lane < 8) st[lane] = it - t;
    }
    __syncthreads();
    uint32_t r = (inc - v) + st[w];
    __syncthreads();
    return r;
}

// ---- block exclusive scan (packed u64), fallback tie path ----
__device__ __forceinline__ ull block_exscan_u64(ull v, ull* st) {
    const uint32_t full = 0xffffffffu;
    int lane = threadIdx.x & 31, w = threadIdx.x >> 5;
    ull inc = v;
#pragma unroll
    for (int o = 1; o < 32; o <<= 1) {
        ull t = __shfl_up_sync(full, inc, o);
        if (lane >= o) inc += t;
    }
    if (lane == 31) st[w] = inc;
    __syncthreads();
    if (threadIdx.x < 32) {
        ull t = (lane < 8) ? st[lane] : 0ull;
        ull it = t;
#pragma unroll
        for (int o = 1; o < 8; o <<= 1) {
            ull x = __shfl_up_sync(full, it, o);
            if (lane >= o) it += x;
        }
        if (lane < 8) st[lane] = it - t;
    }
    __syncthreads();
    ull r = (inc - v) + st[w];
    __syncthreads();
    return r;
}

// ---- RARE fallback: exact radix select (11/11/10), LDG reloads ----
__device__ uint32_t radix_one_g(const float4* rp, uint32_t rank,
                                uint32_t* hist, uint32_t* st, uint32_t* pubT) {
    const int tid = threadIdx.x;
    uint32_t pfx = 0, r = rank;
#pragma unroll
    for (int rnd = 0; rnd < 3; rnd++) {
        reinterpret_cast<uint4*>(hist)[tid] = make_uint4(0, 0, 0, 0);
        reinterpret_cast<uint4*>(hist)[NT + tid] = make_uint4(0, 0, 0, 0);
        __syncthreads();
#pragma unroll
        for (int k2 = 0; k2 < 2; k2++) {
            float4 v = __ldg(&rp[tid + k2 * NT]);
            float sv[4] = {v.x, v.y, v.z, v.w};
#pragma unroll
            for (int c = 0; c < 4; c++) {
                uint32_t u = f2u(sv[c]);
                bool ok; uint32_t bin;
                if (rnd == 0)      { ok = true;                bin = u >> 21; }
                else if (rnd == 1) { ok = (u >> 21) == pfx;    bin = (u >> 10) & 0x7FFu; }
                else               { ok = (u >> 10) == pfx;    bin = u & 0x3FFu; }
                if (ok) atomicAdd(&hist[bin], 1u);
            }
        }
        __syncthreads();
        const int nb = (rnd == 2) ? 4 : 8;
        uint32_t c[8], sum = 0;
#pragma unroll
        for (int k = 0; k < 8; k++) {
            c[k] = (k < nb) ? hist[tid * nb + k] : 0u;
            sum += c[k];
        }
        uint32_t exc = block_exscan_u32(sum, st);
        if (exc < r && r <= exc + sum) {
            uint32_t run = exc;
#pragma unroll
            for (int k = 0; k < 8; k++) {
                if (k < nb && r > run && r <= run + c[k]) {
                    pubT[0] = tid * nb + k; pubT[1] = r - run;
                }
                run += c[k];
            }
        }
        __syncthreads();
        uint32_t bin = pubT[0]; r = pubT[1];
        __syncthreads();
        pfx = (rnd == 2) ? ((pfx << 10) | bin) : ((pfx << 11) | bin);
    }
    return pfx;
}

// ---- RARE fallback: fully handle one row (select+sums+write, exact, LDG) ----
__device__ void fallback_row(const float4* rp, float4* oL, float4* oS,
                             uint32_t* hist, uint32_t* st32, ull* st64,
                             uint32_t* pubT, ull* fsredu, float* fsredf) {
    const uint32_t full = 0xffffffffu;
    const int tid = threadIdx.x, lane = tid & 31, wid = tid >> 5;
    uint32_t kW = radix_one_g(rp, RANKW, hist, st32, pubT);
    uint32_t kL = radix_one_g(rp, RANKL, hist, st32, pubT);
    float swv = u2f(kW), slv = u2f(kL);
    ull packed = 0ull;
    float a2 = 0.0f, b2 = 0.0f;
#pragma unroll
    for (int k2 = 0; k2 < 2; k2++) {
        float4 v = __ldg(&rp[tid + k2 * NT]);
        float sv[4] = {v.x, v.y, v.z, v.w};
#pragma unroll
        for (int c = 0; c < 4; c++) {
            float s = sv[c];
            bool gtW = (s > swv), eqW = (s == swv), ltL = (s < slv), eqL = (s == slv);
            float ex = __expf(gtW ? (s - SHW) : (SHL - s));
            a2 += gtW ? ex : 0.0f;
            b2 += ltL ? ex : 0.0f;
            packed += (ull)gtW + ((ull)eqW << 16) + ((ull)ltL << 32) + ((ull)eqL << 48);
        }
    }
#pragma unroll
    for (int o = 16; o; o >>= 1) {
        packed += __shfl_xor_sync(full, packed, o);
        a2 += __shfl_xor_sync(full, a2, o);
        b2 += __shfl_xor_sync(full, b2, o);
    }
    if (lane == 0) { fsredu[wid] = packed; fsredf[wid] = a2; fsredf[8 + wid] = b2; }
    __syncthreads();
    if (tid < 32) {
        ull c = (lane < 8) ? fsredu[lane] : 0ull;
        float a = (lane < 8) ? fsredf[lane] : 0.0f;
        float b = (lane < 8) ? fsredf[8 + lane] : 0.0f;
#pragma unroll
        for (int o = 4; o; o >>= 1) {
            c += __shfl_xor_sync(full, c, o);
            a += __shfl_xor_sync(full, a, o);
            b += __shfl_xor_sync(full, b, o);
        }
        if (lane == 0) { fsredu[0] = c; fsredf[0] = a; fsredf[8] = b; }
    }
    __syncthreads();
    packed = fsredu[0];
    float sW = fsredf[0], sL = fsredf[8];
    const int nWgt = (int)(packed & 0xFFFFu);
    const int nWeq = (int)((packed >> 16) & 0xFFFFu);
    const int nLlt = (int)((packed >> 32) & 0xFFFFu);
    const int nLeq = (int)((packed >> 48) & 0xFFFFu);
    const int eWc = G - nWgt, eLc = G - nLlt;
    const float expWeq = __expf(swv - SHW);
    const float expLeq = __expf(SHL - slv);
    const float invW = 1.0f / (sW + (float)eWc * expWeq);
    const float invL = 1.0f / (sL + (float)eLc * expLeq);
    const float wEq = expWeq * invW, lEq = expLeq * invL;
    __syncthreads();

    if (nWeq == eWc && nLeq == eLc) {
#pragma unroll
        for (int k = 0; k < 2; k++) {
            float4 v = __ldg(&rp[tid + k * NT]);
            float sv[4] = {v.x, v.y, v.z, v.w};
            float lw[4], sw4[4];
#pragma unroll
            for (int c = 0; c < 4; c++) {
                float s = sv[c];
                bool gtW = (s > swv), ltL = (s < slv);
                float ex = __expf(gtW ? (s - SHW) : (SHL - s));
                lw[c]  = gtW ? ex * invW : ((s == swv) ? wEq : 0.0f);
                sw4[c] = ltL ? ex * invL : ((s == slv) ? lEq : 0.0f);
            }
            oL[tid + k * NT] = make_float4(lw[0], lw[1], lw[2], lw[3]);
            oS[tid + k * NT] = make_float4(sw4[0], sw4[1], sw4[2], sw4[3]);
        }
    } else {
        uint32_t qW0 = 0, qW1 = 0, qL0 = 0, qL1 = 0;
        float fr[8];
#pragma unroll
        for (int k2 = 0; k2 < 2; k2++) {
            float4 v = __ldg(&rp[tid + k2 * NT]);
            fr[k2 * 4 + 0] = v.x; fr[k2 * 4 + 1] = v.y;
            fr[k2 * 4 + 2] = v.z; fr[k2 * 4 + 3] = v.w;
        }
#pragma unroll
        for (int c = 0; c < 4; c++) {
            qW0 += (fr[c] == swv);       qL0 += (fr[c] == slv);
            qW1 += (fr[4 + c] == swv);   qL1 += (fr[4 + c] == slv);
        }
        ull pk = (ull)qW0 | ((ull)qW1 << 16) | ((ull)qL0 << 32) | ((ull)qL1 << 48);
        ull ex2 = block_exscan_u64(pk, st64);
        if (tid == NT - 1) fsredu[7] = ex2 + pk;
        __syncthreads();
        ull tot = fsredu[7];
        const uint32_t totW0 = (uint32_t)(tot & 0xFFFFull);
        const uint32_t totL0 = (uint32_t)((tot >> 32) & 0xFFFFull);
#pragma unroll
        for (int k = 0; k < 2; k++) {
            uint32_t beforeW = k ? totW0 + (uint32_t)((ex2 >> 16) & 0xFFFFull)
                                 : (uint32_t)(ex2 & 0xFFFFull);
            uint32_t beforeL = k ? totL0 + (uint32_t)((ex2 >> 48) & 0xFFFFull)
                                 : (uint32_t)((ex2 >> 32) & 0xFFFFull);
            float lw[4], sw4[4];
#pragma unroll
            for (int c = 0; c < 4; c++) {
                float s = fr[k * 4 + c];
                float lval = 0.0f, sval = 0.0f;
                if (s > swv) lval = __expf(s - SHW) * invW;
                else if (s == swv) { lval = (beforeW < (uint32_t)eWc) ? wEq : 0.0f; beforeW++; }
                if (s < slv) sval = __expf(SHL - s) * invL;
                else if (s == slv) { sval = (beforeL < (uint32_t)eLc) ? lEq : 0.0f; beforeL++; }
                lw[c] = lval;
                sw4[c] = sval;
            }
            oL[tid + k * NT] = make_float4(lw[0], lw[1], lw[2], lw[3]);
            oS[tid + k * NT] = make_float4(sw4[0], sw4[1], sw4[2], sw4[3]);
        }
        __syncthreads();
    }
}

__global__ __launch_bounds__(NT, 7)
void portfolio_kernel(const float* __restrict__ scores,
                      const float* __restrict__ short_ratio,
                      float* __restrict__ out) {
    const int row0 = blockIdx.x * 2;
    const int tid = threadIdx.x;
    const int lane = tid & 31;
    const int wid = tid >> 5;
    const uint32_t full = 0xffffffffu;

    __shared__ float4 srow[2][S / 4];                 // 16 KB: ex values
    __shared__ uint32_t hcnt[2 * NT];                 // 2 KB
    __shared__ float    hexp[2 * NT];                 // 2 KB
    __shared__ __align__(16) uint32_t uwin[2048];     // 8 KB: winS[0..1023], winP[1024..2047]; fallback radix hist
    __shared__ ull fkey[4][FCAP];                     // 1 KB
    __shared__ uint32_t cwin[4], fcnt[4];
    __shared__ uint32_t st32[8];
    __shared__ ull st64[8];
    __shared__ float stf[16];
    __shared__ uint32_t pubW[2][4], pubL[2][4];       // bin, rankInBin, cntInBin, expPref(bits)
    __shared__ uint32_t totE[2];
    __shared__ uint32_t pub2[12];                     // per list: selHi, selLo, cs
    __shared__ uint32_t pubT[2];
    __shared__ ull fsredu[8];
    __shared__ float fsredf[16];

    const float4* rp0 = reinterpret_cast<const float4*>(scores + (size_t)row0 * S);
    const float4* rp1 = reinterpret_cast<const float4*>(scores + (size_t)(row0 + 1) * S);

    hcnt[tid] = 0; hcnt[NT + tid] = 0;
    hexp[tid] = 0.0f; hexp[NT + tid] = 0.0f;
    if (tid < 4) { cwin[tid] = 0; fcnt[tid] = 0; }
    __syncthreads();

    // ---- fused load + histograms + exp + window capture; srow <- ex ----
    uint32_t pb0[2], pb1[2];
#pragma unroll
    for (int k2 = 0; k2 < 2; k2++) {
#pragma unroll
        for (int h = 0; h < 2; h++) {
            float4 v = h ? rp1[tid + k2 * NT] : rp0[tid + k2 * NT];
            float sv[4] = {v.x, v.y, v.z, v.w};
            float exq[4];
            uint32_t pbk = 0;
#pragma unroll
            for (int c = 0; c < 4; c++) {
                float s = sv[c];
                int b = val2bin(s);
                float ex = __expf((b >= 128) ? (s - SHW) : (SHL - s));
                exq[c] = ex;
                pbk |= ((uint32_t)b) << (c * 8);
                atomicAdd(&hcnt[h * NT + b], 1u);
                atomicAdd(&hexp[h * NT + b], ex);
                uint32_t pos = (uint32_t)((tid + k2 * NT) * 4 + c);
                if (b >= WLO && b <= WHI) {
                    uint32_t i = atomicAdd(&cwin[h * 2], 1u);
                    if (i < WCAP) {
                        uwin[(h * 2) * WCAP + i] = __float_as_uint(s);
                        uwin[1024 + (h * 2) * WCAP + i] = pos;
                    }
                }
                if (b >= LLO && b <= LHI) {
                    uint32_t i = atomicAdd(&cwin[h * 2 + 1], 1u);
                    if (i < WCAP) {
                        uwin[(h * 2 + 1) * WCAP + i] = __float_as_uint(s);
                        uwin[1024 + (h * 2 + 1) * WCAP + i] = pos;
                    }
                }
            }
            srow[h][tid + k2 * NT] = make_float4(exq[0], exq[1], exq[2], exq[3]);
            if (h) pb1[k2] = pbk; else pb0[k2] = pbk;
        }
    }
    __syncthreads();

    // ---- fused scans: u64 counts (both rows) + two float exp prefixes ----
    {
        uint32_t ca = hcnt[tid], cb = hcnt[NT + tid];
        float fa = hexp[tid], fb = hexp[NT + tid];
        ull cc = (ull)ca | ((ull)cb << 32);
        ull ci = cc; float fai = fa, fbi = fb;
#pragma unroll
        for (int o = 1; o < 32; o <<= 1) {
            ull t = __shfl_up_sync(full, ci, o);
            float ta = __shfl_up_sync(full, fai, o);
            float tb = __shfl_up_sync(full, fbi, o);
            if (lane >= o) { ci += t; fai += ta; fbi += tb; }
        }
        if (lane == 31) { st64[wid] = ci; stf[wid] = fai; stf[8 + wid] = fbi; }
        __syncthreads();
        if (tid < 32) {
            ull t = (lane < 8) ? st64[lane] : 0ull;
            float a = (lane < 8) ? stf[lane] : 0.0f;
            float b = (lane < 8) ? stf[8 + lane] : 0.0f;
            ull it = t; float ia = a, ib = b;
#pragma unroll
            for (int o = 1; o < 8; o <<= 1) {
                ull x = __shfl_up_sync(full, it, o);
                float xa = __shfl_up_sync(full, ia, o);
                float xb = __shfl_up_sync(full, ib, o);
                if (lane >= o) { it += x; ia += xa; ib += xb; }
            }
            if (lane < 8) { st64[lane] = it - t; stf[lane] = ia - a; stf[8 + lane] = ib - b; }
        }
        __syncthreads();
        ull ce = (ci - cc) + st64[wid];
        float fae = (fai - fa) + stf[wid];
        float fbe = (fbi - fb) + stf[8 + wid];
        uint32_t ea = (uint32_t)ce, eb = (uint32_t)(ce >> 32);
        if (ea < RANKW && RANKW <= ea + ca) {
            pubW[0][0] = tid; pubW[0][1] = RANKW - ea; pubW[0][2] = ca;
            pubW[0][3] = __float_as_uint(fae + fa);
        }
        if (ea < RANKL && RANKL <= ea + ca) {
            pubL[0][0] = tid; pubL[0][1] = RANKL - ea; pubL[0][2] = ca;
            pubL[0][3] = __float_as_uint(fae);
        }
        if (eb < RANKW && RANKW <= eb + cb) {
            pubW[1][0] = tid; pubW[1][1] = RANKW - eb; pubW[1][2] = cb;
            pubW[1][3] = __float_as_uint(fbe + fb);
        }
        if (eb < RANKL && RANKL <= eb + cb) {
            pubL[1][0] = tid; pubL[1][1] = RANKL - eb; pubL[1][2] = cb;
            pubL[1][3] = __float_as_uint(fbe);
        }
        if (tid == NT - 1) {
            totE[0] = __float_as_uint(fae + fa);
            totE[1] = __float_as_uint(fbe + fb);
        }
        __syncthreads();
    }

    // ---- filter window lists into <=32 candidate keys per list ----
#pragma unroll
    for (int i = 0; i < 4; i++) {
        uint32_t n = min(cwin[i], (uint32_t)WCAP);
        if ((uint32_t)tid < n) {
            float s = __uint_as_float(uwin[i * WCAP + tid]);
            uint32_t pos = uwin[1024 + i * WCAP + tid];
            int b = val2bin(s);
            int target = (i & 1) ? (int)pubL[i >> 1][0] : (int)pubW[i >> 1][0];
            if (b == target) {
                uint32_t j = atomicAdd(&fcnt[i], 1u);
                if (j < FCAP) {
                    uint32_t lo = (i & 1) ? pos : (2047u - pos);
                    fkey[i][j] = ((ull)f2u(s) << 32) | (ull)lo;
                }
            }
        }
    }
    __syncthreads();

    // ---- fast-path validity (block-uniform) ----
    bool fastH[2];
#pragma unroll
    for (int h = 0; h < 2; h++) {
        int bW = (int)pubW[h][0], bL = (int)pubL[h][0];
        fastH[h] = (bW >= WLO && bW <= WHI) && (bL >= LLO && bL <= LHI) &&
                   (cwin[h * 2] <= WCAP) && (cwin[h * 2 + 1] <= WCAP) &&
                   (pubW[h][2] <= FCAP) && (pubL[h][2] <= FCAP);
    }

    // ---- warps 0-3: sort candidate composites, select threshold, ballot sums ----
    if (wid < 4 && fastH[wid >> 1]) {
        const int side = wid & 1;
        const uint32_t n = fcnt[wid];
        ull key = ((uint32_t)lane < n) ? fkey[wid][lane] : 0xFFFFFFFFFFFFFFFFull;
#pragma unroll
        for (int k = 2; k <= 32; k <<= 1) {
#pragma unroll
            for (int j = k >> 1; j > 0; j >>= 1) {
                ull o = __shfl_xor_sync(full, key, j);
                bool up = ((lane & k) == 0);
                bool lower = ((lane & j) == 0);
                ull mn = (key < o) ? key : o;
                ull mx = (key < o) ? o : key;
                key = (lower == up) ? mn : mx;
            }
        }
        uint32_t rank = side ? pubL[wid >> 1][1] : pubW[wid >> 1][1];  // 1-based
        ull sel = __shfl_sync(full, key, (int)(rank - 1));
        bool valid = ((uint32_t)lane < n);
        bool inc = valid && (side ? (key <= sel) : (key >= sel));
        float s = u2f((uint32_t)(key >> 32));
        float cs = inc ? __expf(side ? (SHL - s) : (s - SHW)) : 0.0f;
#pragma unroll
        for (int o = 16; o; o >>= 1) cs += __shfl_xor_sync(full, cs, o);
        if (lane == 0) {
            pub2[wid * 3 + 0] = (uint32_t)(sel >> 32);
            pub2[wid * 3 + 1] = (uint32_t)sel;
            pub2[wid * 3 + 2] = __float_as_uint(cs);
        }
    }
    __syncthreads();

    // ---- RARE fallbacks (fully handle their rows) ----
    if (!fastH[0])
        fallback_row(rp0, reinterpret_cast<float4*>(out + (size_t)row0 * S),
                     reinterpret_cast<float4*>(out + (size_t)BATCH * S + (size_t)row0 * S),
                     uwin, st32, st64, pubT, fsredu, fsredf);
    if (!fastH[1])
        fallback_row(rp1, reinterpret_cast<float4*>(out + (size_t)(row0 + 1) * S),
                     reinterpret_cast<float4*>(out + (size_t)BATCH * S + (size_t)(row0 + 1) * S),
                     uwin, st32, st64, pubT, fsredu, fsredf);

    // ---- fast main writes (bin-classified, ex from srow; crossing bins -> 0) ----
#pragma unroll
    for (int h = 0; h < 2; h++) {
        if (!fastH[h]) continue;
        const int binW = (int)pubW[h][0], binL = (int)pubL[h][0];
        const float sW = __uint_as_float(totE[h]) - __uint_as_float(pubW[h][3])
                       + __uint_as_float(pub2[(h * 2) * 3 + 2]);
        const float sL = __uint_as_float(pubL[h][3])
                       + __uint_as_float(pub2[(h * 2 + 1) * 3 + 2]);
        const float invW = 1.0f / sW, invL = 1.0f / sL;
        float4* oL = reinterpret_cast<float4*>(out + (size_t)(row0 + h) * S);
        float4* oS = reinterpret_cast<float4*>(out + (size_t)BATCH * S + (size_t)(row0 + h) * S);
#pragma unroll
        for (int k = 0; k < 2; k++) {
            float4 e4 = srow[h][tid + k * NT];
            float ev[4] = {e4.x, e4.y, e4.z, e4.w};
            uint32_t pbk = h ? pb1[k] : pb0[k];
            float lw[4], sw4[4];
#pragma unroll
            for (int c = 0; c < 4; c++) {
                int b = (int)((pbk >> (c * 8)) & 0xFFu);
                lw[c]  = (b > binW) ? ev[c] * invW : 0.0f;
                sw4[c] = (b < binL) ? ev[c] * invL : 0.0f;
            }
            oL[tid + k * NT] = make_float4(lw[0], lw[1], lw[2], lw[3]);
            oS[tid + k * NT] = make_float4(sw4[0], sw4[1], sw4[2], sw4[3]);
        }
    }
    __syncthreads();

    // ---- fix-up scatter for crossing-bin candidates ----
    if (wid < 4 && fastH[wid >> 1]) {
        const int h = wid >> 1, side = wid & 1;
        const uint32_t n = fcnt[wid];
        if ((uint32_t)lane < n) {
            ull key = fkey[wid][lane];
            ull sel = ((ull)pub2[wid * 3 + 0] << 32) | (ull)pub2[wid * 3 + 1];
            bool inc = side ? (key <= sel) : (key >= sel);
            float s = u2f((uint32_t)(key >> 32));
            float cs = __uint_as_float(pub2[wid * 3 + 2]);
            float den = side
                ? (__uint_as_float(pubL[h][3]) + cs)
                : (__uint_as_float(totE[h]) - __uint_as_float(pubW[h][3]) + cs);
            float val = inc ? __expf(side ? (SHL - s) : (s - SHW)) / den : 0.0f;
            uint32_t pos = side ? (uint32_t)(key & 0xFFFFFFFFull)
                                : (2047u - (uint32_t)(key & 0xFFFFFFFFull));
            size_t base = side ? ((size_t)BATCH * S + (size_t)(row0 + h) * S)
                               : ((size_t)(row0 + h) * S);
            out[base + pos] = val;
        }
    }

    // ---- short_ratio passthrough (clipped) ----
    if (tid < 2) {
        float r = short_ratio[row0 + tid];
        r = fminf(fmaxf(r, 0.0f), 1.0f);
        out[(size_t)2 * BATCH * S + row0 + tid] = r;
    }
}

extern "C" void kernel_launch(void* const* d_in, const int* in_sizes, int n_in,
                              void* d_out, int out_size) {
    const float* scores = (const float*)d_in[0];
    const float* ratio  = (const float*)d_in[1];
    if (n_in >= 2 && in_sizes[0] == BATCH && in_sizes[1] == BATCH * S) {
        const float* t = scores; scores = ratio; ratio = t;
    }
    portfolio_kernel<<<BATCH / 2, NT>>>(scores, ratio, (float*)d_out);
}